// round 1
// baseline (speedup 1.0000x reference)
#include <cuda_runtime.h>
#include <stdint.h>

#define BB 8
#define NN 16384
#define SS 2048
#define CC 64
#define KK 32
#define COUT (3 + CC)   // 67

// Scratch for ball-query indices (no cudaMalloc allowed).
__device__ __align__(16) int g_idx[BB * SS * KK];

// ---------------------------------------------------------------------------
// Kernel 1: warp-per-center ball query with early exit.
// Reference semantics: smallest 32 indices j with |c-p_j|^2 < 0.04 (ascending),
// padded with the first found index, or 0 if none found.
// ---------------------------------------------------------------------------
__global__ __launch_bounds__(256) void ball_query_kernel(
    const float* __restrict__ points,   // (B, N, 3)
    const float* __restrict__ centers)  // (B, S, 3)
{
    const int wid  = threadIdx.x >> 5;
    const int lane = threadIdx.x & 31;
    const int gw   = blockIdx.x * (blockDim.x >> 5) + wid;  // global warp id = b*S+s
    const int b = gw / SS;
    const int s = gw % SS;

    const float* cptr = centers + (size_t)(b * SS + s) * 3;
    const float cx = __ldg(cptr + 0);
    const float cy = __ldg(cptr + 1);
    const float cz = __ldg(cptr + 2);

    __shared__ int sel[8][KK];   // 8 warps per block

    const float* pbase = points + (size_t)b * NN * 3;
    const float R2 = 0.04f;     // float(0.2**2), matches f32 rounding of the ref

    int cnt = 0;
    for (int t = 0; t < NN / 32; ++t) {
        const int j = t * 32 + lane;
        const float px = __ldg(pbase + 3 * j + 0);
        const float py = __ldg(pbase + 3 * j + 1);
        const float pz = __ldg(pbase + 3 * j + 2);
        // No FMA contraction: match XLA's sub/square/sequential-sum ordering.
        const float dx = __fadd_rn(cx, -px);
        const float dy = __fadd_rn(cy, -py);
        const float dz = __fadd_rn(cz, -pz);
        const float d2 = __fadd_rn(__fadd_rn(__fmul_rn(dx, dx), __fmul_rn(dy, dy)),
                                   __fmul_rn(dz, dz));
        const bool hit = d2 < R2;
        const unsigned m = __ballot_sync(0xffffffffu, hit);
        if (hit) {
            const int pos = cnt + __popc(m & ((1u << lane) - 1u));
            if (pos < KK) sel[wid][pos] = j;
        }
        cnt += __popc(m);
        if (cnt >= KK) break;   // warp-uniform early exit
    }
    __syncwarp();

    int v;
    if (cnt == 0) {
        v = 0;
    } else {
        const int first = sel[wid][0];
        v = (lane < cnt) ? sel[wid][lane] : first;
    }
    g_idx[(size_t)gw * KK + lane] = v;   // coalesced 128B per warp
}

// ---------------------------------------------------------------------------
// Kernel 2: one block per (b, out-channel) plane.
// Stage the 64KB source row in shared memory, gather via LDS, coalesced
// float4 stores. co<3 -> points component (minus center), co>=3 -> feature row.
// ---------------------------------------------------------------------------
__global__ __launch_bounds__(512) void gather_kernel(
    const float* __restrict__ points,   // (B, N, 3)
    const float* __restrict__ centers,  // (B, S, 3)
    const float* __restrict__ feats,    // (B, C, N)
    float* __restrict__ out)            // (B, 67, S, K)
{
    extern __shared__ float row[];      // NN floats = 64KB

    const int plane = blockIdx.x;       // 0 .. B*67-1
    const int b  = plane / COUT;
    const int co = plane % COUT;
    const bool isxyz = (co < 3);

    if (isxyz) {
        const float* p = points + (size_t)b * NN * 3 + co;
        for (int i = threadIdx.x; i < NN; i += blockDim.x)
            row[i] = __ldg(p + 3 * i);
    } else {
        const float4* f4 = (const float4*)(feats + ((size_t)b * CC + (co - 3)) * NN);
        float4* r4 = (float4*)row;
        for (int i = threadIdx.x; i < NN / 4; i += blockDim.x)
            r4[i] = __ldg(f4 + i);
    }
    __syncthreads();

    const int4*  idx4 = (const int4*)(g_idx + (size_t)b * SS * KK);
    float4*      out4 = (float4*)(out + (size_t)plane * SS * KK);
    const float* cbase = centers + (size_t)b * SS * 3 + co;

    const int total4 = SS * KK / 4;     // 16384 float4 per plane
    for (int i = threadIdx.x; i < total4; i += blockDim.x) {
        const int4 id = __ldg(idx4 + i);
        float4 v;
        v.x = row[id.x];
        v.y = row[id.y];
        v.z = row[id.z];
        v.w = row[id.w];
        if (isxyz) {
            const int s = i >> 3;       // 8 groups of 4 per center (K=32)
            const float cv = __ldg(cbase + 3 * s);
            v.x -= cv; v.y -= cv; v.z -= cv; v.w -= cv;
        }
        out4[i] = v;
    }
}

// ---------------------------------------------------------------------------
extern "C" void kernel_launch(void* const* d_in, const int* in_sizes, int n_in,
                              void* d_out, int out_size)
{
    const float* points  = (const float*)d_in[0];  // 8*16384*3
    const float* centers = (const float*)d_in[1];  // 8*2048*3
    const float* feats   = (const float*)d_in[2];  // 8*64*16384
    float* out = (float*)d_out;                    // 8*67*2048*32

    (void)in_sizes; (void)n_in; (void)out_size;

    // 64KB dynamic smem needs the opt-in attribute (not a stream op; capture-safe).
    static_assert(NN * sizeof(float) == 65536, "row size");
    cudaFuncSetAttribute(gather_kernel,
                         cudaFuncAttributeMaxDynamicSharedMemorySize,
                         NN * (int)sizeof(float));

    // Kernel 1: 16384 warps, 8 per block.
    ball_query_kernel<<<BB * SS / 8, 256>>>(points, centers);

    // Kernel 2: one block per output plane.
    gather_kernel<<<BB * COUT, 512, NN * sizeof(float)>>>(points, centers, feats, out);
}

// round 2
// speedup vs baseline: 1.0087x; 1.0087x over previous
#include <cuda_runtime.h>
#include <stdint.h>

#define BB 8
#define NN 16384
#define SS 2048
#define CC 64
#define KK 32
#define COUT (3 + CC)   // 67

// Scratch for ball-query indices (no cudaMalloc allowed).
__device__ __align__(16) int g_idx[BB * SS * KK];

// ---------------------------------------------------------------------------
// Kernel 1: warp-per-center ball query with early exit.
// Reference semantics: smallest 32 indices j with |c-p_j|^2 < 0.04 (ascending),
// padded with the first found index, or 0 if none found.
// ---------------------------------------------------------------------------
__global__ __launch_bounds__(256) void ball_query_kernel(
    const float* __restrict__ points,   // (B, N, 3)
    const float* __restrict__ centers)  // (B, S, 3)
{
    const int wid  = threadIdx.x >> 5;
    const int lane = threadIdx.x & 31;
    const int gw   = blockIdx.x * (blockDim.x >> 5) + wid;  // global warp id = b*S+s
    const int b = gw / SS;
    const int s = gw % SS;

    const float* cptr = centers + (size_t)(b * SS + s) * 3;
    const float cx = __ldg(cptr + 0);
    const float cy = __ldg(cptr + 1);
    const float cz = __ldg(cptr + 2);

    __shared__ int sel[8][KK];   // 8 warps per block

    const float* pbase = points + (size_t)b * NN * 3;
    const float R2 = 0.04f;     // float(0.2**2), matches f32 rounding of the ref

    int cnt = 0;
    for (int t = 0; t < NN / 32; ++t) {
        const int j = t * 32 + lane;
        const float px = __ldg(pbase + 3 * j + 0);
        const float py = __ldg(pbase + 3 * j + 1);
        const float pz = __ldg(pbase + 3 * j + 2);
        // No FMA contraction: match XLA's sub/square/sequential-sum ordering.
        const float dx = __fadd_rn(cx, -px);
        const float dy = __fadd_rn(cy, -py);
        const float dz = __fadd_rn(cz, -pz);
        const float d2 = __fadd_rn(__fadd_rn(__fmul_rn(dx, dx), __fmul_rn(dy, dy)),
                                   __fmul_rn(dz, dz));
        const bool hit = d2 < R2;
        const unsigned m = __ballot_sync(0xffffffffu, hit);
        if (hit) {
            const int pos = cnt + __popc(m & ((1u << lane) - 1u));
            if (pos < KK) sel[wid][pos] = j;
        }
        cnt += __popc(m);
        if (cnt >= KK) break;   // warp-uniform early exit
    }
    __syncwarp();

    int v;
    if (cnt == 0) {
        v = 0;
    } else {
        const int first = sel[wid][0];
        v = (lane < cnt) ? sel[wid][lane] : first;
    }
    g_idx[(size_t)gw * KK + lane] = v;   // coalesced 128B per warp
}

// ---------------------------------------------------------------------------
// Kernel 2: one block per (b, out-channel) plane.
// Stage the 64KB source row in shared memory, gather via LDS, coalesced
// float4 stores. co<3 -> points component (minus center), co>=3 -> feature row.
// ---------------------------------------------------------------------------
__global__ __launch_bounds__(512) void gather_kernel(
    const float* __restrict__ points,   // (B, N, 3)
    const float* __restrict__ centers,  // (B, S, 3)
    const float* __restrict__ feats,    // (B, C, N)
    float* __restrict__ out)            // (B, 67, S, K)
{
    extern __shared__ float row[];      // NN floats = 64KB

    const int plane = blockIdx.x;       // 0 .. B*67-1
    const int b  = plane / COUT;
    const int co = plane % COUT;
    const bool isxyz = (co < 3);

    if (isxyz) {
        const float* p = points + (size_t)b * NN * 3 + co;
        for (int i = threadIdx.x; i < NN; i += blockDim.x)
            row[i] = __ldg(p + 3 * i);
    } else {
        const float4* f4 = (const float4*)(feats + ((size_t)b * CC + (co - 3)) * NN);
        float4* r4 = (float4*)row;
        for (int i = threadIdx.x; i < NN / 4; i += blockDim.x)
            r4[i] = __ldg(f4 + i);
    }
    __syncthreads();

    const int4*  idx4 = (const int4*)(g_idx + (size_t)b * SS * KK);
    float4*      out4 = (float4*)(out + (size_t)plane * SS * KK);
    const float* cbase = centers + (size_t)b * SS * 3 + co;

    const int total4 = SS * KK / 4;     // 16384 float4 per plane
    for (int i = threadIdx.x; i < total4; i += blockDim.x) {
        const int4 id = __ldg(idx4 + i);
        float4 v;
        v.x = row[id.x];
        v.y = row[id.y];
        v.z = row[id.z];
        v.w = row[id.w];
        if (isxyz) {
            const int s = i >> 3;       // 8 groups of 4 per center (K=32)
            const float cv = __ldg(cbase + 3 * s);
            v.x -= cv; v.y -= cv; v.z -= cv; v.w -= cv;
        }
        out4[i] = v;
    }
}

// ---------------------------------------------------------------------------
extern "C" void kernel_launch(void* const* d_in, const int* in_sizes, int n_in,
                              void* d_out, int out_size)
{
    const float* points  = (const float*)d_in[0];  // 8*16384*3
    const float* centers = (const float*)d_in[1];  // 8*2048*3
    const float* feats   = (const float*)d_in[2];  // 8*64*16384
    float* out = (float*)d_out;                    // 8*67*2048*32

    (void)in_sizes; (void)n_in; (void)out_size;

    // 64KB dynamic smem needs the opt-in attribute (not a stream op; capture-safe).
    static_assert(NN * sizeof(float) == 65536, "row size");
    cudaFuncSetAttribute(gather_kernel,
                         cudaFuncAttributeMaxDynamicSharedMemorySize,
                         NN * (int)sizeof(float));

    // Kernel 1: 16384 warps, 8 per block.
    ball_query_kernel<<<BB * SS / 8, 256>>>(points, centers);

    // Kernel 2: one block per output plane.
    gather_kernel<<<BB * COUT, 512, NN * sizeof(float)>>>(points, centers, feats, out);
}